// round 11
// baseline (speedup 1.0000x reference)
#include <cuda_runtime.h>
#include <cstdint>
#include <math.h>

// ---------------------------------------------------------------------------
// Problem constants
// ---------------------------------------------------------------------------
#define B_ROWS 8192
#define IN_F   4096
#define OUT_F  4096
#define NFRAG  16
#define FS     256
#define COMP   1024

// GEMM tiling: int8 dual-digit
#define BM 128
#define BN 128
#define BK 64            // int8 elements per stage (64 bytes per row)
#define NSTAGE 3

#define A_TB   (128 * 64)                 // one 128x64 int8 tile = 8 KB
#define STAGE_B (4 * A_TB)                // Ad1, Ad2, Bd1, Bd2 = 32 KB
#define SMEM_DYN (NSTAGE * STAGE_B)       // 96 KB

// swizzle: 64B rows, 4x16B chunks; chunk ^= (row>>1)&3  (conflict-free LDSM)
#define SWZ(r, c) ((((c) ^ (((r) >> 1) & 3)) << 4))

// ---------------------------------------------------------------------------
// Scratch (static device globals; no runtime allocation)
// ---------------------------------------------------------------------------
__device__ float g_probs[B_ROWS * NFRAG];

__device__ __align__(16) int8_t g_ad1 [B_ROWS * IN_F];   // digits of a = x*p
__device__ __align__(16) int8_t g_ad2 [B_ROWS * IN_F];
__device__ __align__(16) int8_t g_md1 [B_ROWS * IN_F];   // digits of m = x - a
__device__ __align__(16) int8_t g_md2 [B_ROWS * IN_F];
__device__ __align__(16) int8_t g_wtd1[OUT_F * IN_F];    // We^T [N,K]
__device__ __align__(16) int8_t g_wtd2[OUT_F * IN_F];
__device__ __align__(16) int8_t g_wcd1[COMP * IN_F];     // Wc [N,K]
__device__ __align__(16) int8_t g_wcd2[COMP * IN_F];
__device__ __align__(16) int8_t g_wnd1[OUT_F * COMP];    // Wn [N,K]
__device__ __align__(16) int8_t g_wnd2[OUT_F * COMP];
__device__ __align__(16) int8_t g_c1d1[B_ROWS * COMP];   // compressed digits
__device__ __align__(16) int8_t g_c1d2[B_ROWS * COMP];
__device__ __align__(16) float  g_c1f [B_ROWS * COMP];   // compressed fp32

__device__ float g_s_a [B_ROWS];   // row scales
__device__ float g_s_m [B_ROWS];
__device__ float g_s_c1[B_ROWS];
__device__ float g_t_we[OUT_F];    // col-max of We (atomicMax int-bits)
__device__ float g_t_wc[COMP];
__device__ float g_t_wn[OUT_F];

// ---------------------------------------------------------------------------
// Helpers (family-safe PTX only: cp.async, ldmatrix, int8 mma.sync)
// ---------------------------------------------------------------------------
__device__ __forceinline__ uint32_t smem_u32(const void* p) {
    uint32_t a;
    asm("{ .reg .u64 t; cvta.to.shared.u64 t, %1; cvt.u32.u64 %0, t; }"
        : "=r"(a) : "l"(p));
    return a;
}
__device__ __forceinline__ void cp16(uint32_t dst, const void* src) {
    asm volatile("cp.async.cg.shared.global [%0], [%1], 16;" :: "r"(dst), "l"(src));
}
__device__ __forceinline__ void cp_commit() {
    asm volatile("cp.async.commit_group;");
}
__device__ __forceinline__ void cp_wait1() {
    asm volatile("cp.async.wait_group 1;" ::: "memory");
}
__device__ __forceinline__ void ldsm4(uint32_t* f, uint32_t a) {
    asm volatile("ldmatrix.sync.aligned.m8n8.x4.shared.b16 {%0,%1,%2,%3}, [%4];"
                 : "=r"(f[0]), "=r"(f[1]), "=r"(f[2]), "=r"(f[3]) : "r"(a));
}
__device__ __forceinline__ void imma(int* d, const uint32_t* a, uint32_t b0, uint32_t b1) {
    asm volatile(
        "mma.sync.aligned.m16n8k32.row.col.s32.s8.s8.s32 "
        "{%0,%1,%2,%3}, {%4,%5,%6,%7}, {%8,%9}, {%0,%1,%2,%3};"
        : "+r"(d[0]), "+r"(d[1]), "+r"(d[2]), "+r"(d[3])
        : "r"(a[0]), "r"(a[1]), "r"(a[2]), "r"(a[3]), "r"(b0), "r"(b1));
}
// quantize one float given (guarded) row scale s -> (d1, d2)
__device__ __forceinline__ void quant2(float v, float inv_s, int8_t& d1, int8_t& d2) {
    float f = v * inv_s * 127.0f;         // in [-127, 127]
    int q1 = __float2int_rn(f);
    float r = f - (float)q1;              // in [-0.5, 0.5]
    int q2 = __float2int_rn(r * 128.0f);  // in [-64, 64]
    d1 = (int8_t)q1;
    d2 = (int8_t)q2;
}
union PackC4 { int8_t c[4]; uint32_t u; };

// ---------------------------------------------------------------------------
// Gating: softmax over fragment scores
// ---------------------------------------------------------------------------
__global__ void __launch_bounds__(512) gating_kernel(
    const float* __restrict__ x, const float* __restrict__ sel)
{
    int b = blockIdx.x, t = threadIdx.x;
    int w = t >> 5, lane = t & 31;
    const float* xr = x + (size_t)b * IN_F + w * FS;
    const float* sr = sel + w * FS;
    float acc = 0.f;
#pragma unroll
    for (int j = 0; j < 8; j++) acc += xr[lane + 32*j] * sr[lane + 32*j];
#pragma unroll
    for (int o = 16; o; o >>= 1) acc += __shfl_xor_sync(0xFFFFFFFFu, acc, o);
    __shared__ float s[NFRAG];
    if (lane == 0) s[w] = acc;
    __syncthreads();
    if (t < NFRAG) {
        float m = -INFINITY;
#pragma unroll
        for (int f = 0; f < NFRAG; f++) m = fmaxf(m, s[f]);
        float sum = 0.f;
#pragma unroll
        for (int f = 0; f < NFRAG; f++) sum += __expf(s[f] - m);
        g_probs[b * NFRAG + t] = __expf(s[t] - m) / sum;
    }
}

// ---------------------------------------------------------------------------
// quant_am: per row, a = x*p, m = x - a; rowmax both, then quantize digits
// ---------------------------------------------------------------------------
__global__ void __launch_bounds__(256) quant_am(const float* __restrict__ x)
{
    int b = blockIdx.x, t = threadIdx.x;
    const float* xr = x + (size_t)b * IN_F;
    __shared__ float2 red[256];
    __shared__ float sh_s[2];

    float ma = 0.f, mm = 0.f;
#pragma unroll
    for (int it = 0; it < 4; it++) {
        int c4 = (t + it * 256) * 4;
        float p = g_probs[b * NFRAG + (c4 >> 8)];
        float4 v = *(const float4*)(xr + c4);
        float a0 = v.x*p, a1 = v.y*p, a2 = v.z*p, a3 = v.w*p;
        ma = fmaxf(ma, fmaxf(fmaxf(fabsf(a0), fabsf(a1)), fmaxf(fabsf(a2), fabsf(a3))));
        float m0 = v.x-a0, m1 = v.y-a1, m2 = v.z-a2, m3 = v.w-a3;
        mm = fmaxf(mm, fmaxf(fmaxf(fabsf(m0), fabsf(m1)), fmaxf(fabsf(m2), fabsf(m3))));
    }
    red[t] = make_float2(ma, mm);
    __syncthreads();
    for (int s = 128; s; s >>= 1) {
        if (t < s) {
            red[t].x = fmaxf(red[t].x, red[t + s].x);
            red[t].y = fmaxf(red[t].y, red[t + s].y);
        }
        __syncthreads();
    }
    if (t == 0) {
        float sa = fmaxf(red[0].x, 1e-20f), sm = fmaxf(red[0].y, 1e-20f);
        g_s_a[b] = sa; g_s_m[b] = sm;
        sh_s[0] = 1.0f / sa; sh_s[1] = 1.0f / sm;
    }
    __syncthreads();
    float isa = sh_s[0], ism = sh_s[1];

#pragma unroll
    for (int it = 0; it < 4; it++) {
        int c4 = (t + it * 256) * 4;
        float p = g_probs[b * NFRAG + (c4 >> 8)];
        float4 v = *(const float4*)(xr + c4);
        float av[4] = { v.x*p, v.y*p, v.z*p, v.w*p };
        float mv[4] = { v.x-av[0], v.y-av[1], v.z-av[2], v.w-av[3] };
        PackC4 a1, a2, m1, m2;
#pragma unroll
        for (int j = 0; j < 4; j++) {
            quant2(av[j], isa, a1.c[j], a2.c[j]);
            quant2(mv[j], ism, m1.c[j], m2.c[j]);
        }
        size_t o = (size_t)b * IN_F + c4;
        *(uint32_t*)(g_ad1 + o) = a1.u;  *(uint32_t*)(g_ad2 + o) = a2.u;
        *(uint32_t*)(g_md1 + o) = m1.u;  *(uint32_t*)(g_md2 + o) = m2.u;
    }
}

// ---------------------------------------------------------------------------
// We column-max (t_we) then transpose+quantize We -> WeT digits
// ---------------------------------------------------------------------------
__global__ void __launch_bounds__(256) zero_twe()
{
    g_t_we[blockIdx.x * 256 + threadIdx.x] = 0.f;
}
__global__ void __launch_bounds__(256) colmax_we(const float* __restrict__ We)
{
    int r0 = blockIdx.x * 64, t = threadIdx.x;
    for (int c0 = 0; c0 < OUT_F; c0 += 256) {
        int c = c0 + t;
        float m = 0.f;
        for (int r = r0; r < r0 + 64; r++)
            m = fmaxf(m, fabsf(We[(size_t)r * OUT_F + c]));
        atomicMax((int*)(g_t_we + c), __float_as_int(m));
    }
}
__global__ void __launch_bounds__(256) quant_weT(const float* __restrict__ We)
{
    __shared__ float tile[32][33];
    int k0 = blockIdx.y * 32, n0 = blockIdx.x * 32;
    int tx = threadIdx.x, ty = threadIdx.y;
#pragma unroll
    for (int r = 0; r < 4; r++)
        tile[ty + r*8][tx] = We[(size_t)(k0 + ty + r*8) * OUT_F + n0 + tx];
    __syncthreads();
#pragma unroll
    for (int r = 0; r < 4; r++) {
        int n = n0 + ty + r*8, k = k0 + tx;
        float inv_s = 1.0f / fmaxf(g_t_we[n], 1e-20f);
        int8_t d1, d2;
        quant2(tile[tx][ty + r*8], inv_s, d1, d2);
        size_t o = (size_t)n * IN_F + k;
        g_wtd1[o] = d1;
        g_wtd2[o] = d2;
    }
}

// ---------------------------------------------------------------------------
// Generic per-row quantizer: rowmax -> scale + digits  (Wc, Wn, c1)
// ---------------------------------------------------------------------------
__global__ void __launch_bounds__(256) quant_rows(
    const float* __restrict__ src, int L,
    int8_t* __restrict__ d1, int8_t* __restrict__ d2, float* __restrict__ srow)
{
    int b = blockIdx.x, t = threadIdx.x;
    const float* row = src + (size_t)b * L;
    __shared__ float red[256];
    __shared__ float sh_is;

    float m = 0.f;
    for (int c4 = t * 4; c4 < L; c4 += 1024) {
        float4 v = *(const float4*)(row + c4);
        m = fmaxf(m, fmaxf(fmaxf(fabsf(v.x), fabsf(v.y)), fmaxf(fabsf(v.z), fabsf(v.w))));
    }
    red[t] = m;
    __syncthreads();
    for (int s = 128; s; s >>= 1) {
        if (t < s) red[t] = fmaxf(red[t], red[t + s]);
        __syncthreads();
    }
    if (t == 0) {
        float s = fmaxf(red[0], 1e-20f);
        srow[b] = s;
        sh_is = 1.0f / s;
    }
    __syncthreads();
    float inv_s = sh_is;
    for (int c4 = t * 4; c4 < L; c4 += 1024) {
        float4 v = *(const float4*)(row + c4);
        PackC4 p1, p2;
        quant2(v.x, inv_s, p1.c[0], p2.c[0]);
        quant2(v.y, inv_s, p1.c[1], p2.c[1]);
        quant2(v.z, inv_s, p1.c[2], p2.c[2]);
        quant2(v.w, inv_s, p1.c[3], p2.c[3]);
        size_t o = (size_t)b * L + c4;
        *(uint32_t*)(d1 + o) = p1.u;
        *(uint32_t*)(d2 + o) = p2.u;
    }
}

// ---------------------------------------------------------------------------
// int8 dual-digit GEMM:  D[M,N] = A[M,K] . B[N,K]^T
// MODE 0/1: store to dst;  2: dst += (read-modify-write)
// ---------------------------------------------------------------------------
__device__ __forceinline__ void load_stage_i8(
    uint32_t st, const int8_t* Ad1, const int8_t* Ad2,
    const int8_t* Bd1, const int8_t* Bd2,
    int rowBase, int colBase, int ld, int kt)
{
    int t = threadIdx.x;
#pragma unroll
    for (int i = 0; i < 2; i++) {
        int id = t + i * 256;
        int r  = id >> 2;
        int c  = id & 3;
        uint32_t off = (uint32_t)(r * 64 + SWZ(r, c));
        size_t ga = (size_t)(rowBase + r) * ld + kt + c * 16;
        size_t gb = (size_t)(colBase + r) * ld + kt + c * 16;
        cp16(st + off,            Ad1 + ga);
        cp16(st + A_TB + off,     Ad2 + ga);
        cp16(st + 2 * A_TB + off, Bd1 + gb);
        cp16(st + 3 * A_TB + off, Bd2 + gb);
    }
}

__device__ __forceinline__ void compute_stage_i8(
    uint32_t st, int accHi[4][4][4], int accMid[4][4][4], int wm, int wn, int lane)
{
#pragma unroll
    for (int s = 0; s < 2; s++) {                    // two k32 steps
        int arow_lo = (lane & 7) + ((lane >> 3) & 1) * 8;
        int achunk  = 2 * s + (lane >> 4);
        uint32_t ad1[4][4], ad2[4][4];
#pragma unroll
        for (int mi = 0; mi < 4; mi++) {
            int r = wm * 64 + mi * 16 + arow_lo;
            uint32_t off = (uint32_t)(r * 64 + ((achunk ^ ((r >> 1) & 3)) << 4));
            ldsm4(ad1[mi], st + off);
            ldsm4(ad2[mi], st + A_TB + off);
        }
        int brow_lo = (lane & 7) + ((lane >> 4) ? 8 : 0);
        int bchunk  = 2 * s + ((lane >> 3) & 1);
        uint32_t bd1[2][4], bd2[2][4];
#pragma unroll
        for (int g = 0; g < 2; g++) {
            int n = wn * 32 + g * 16 + brow_lo;
            uint32_t off = (uint32_t)(n * 64 + ((bchunk ^ ((n >> 1) & 3)) << 4));
            ldsm4(bd1[g], st + 2 * A_TB + off);
            ldsm4(bd2[g], st + 3 * A_TB + off);
        }
#pragma unroll
        for (int mi = 0; mi < 4; mi++)
#pragma unroll
            for (int nt = 0; nt < 4; nt++) {
                int g = nt >> 1, sub = nt & 1;
                uint32_t bh0 = bd1[g][sub * 2], bh1 = bd1[g][sub * 2 + 1];
                uint32_t bl0 = bd2[g][sub * 2], bl1 = bd2[g][sub * 2 + 1];
                imma(accHi [mi][nt], ad1[mi], bh0, bh1);
                imma(accMid[mi][nt], ad1[mi], bl0, bl1);
                imma(accMid[mi][nt], ad2[mi], bh0, bh1);
            }
    }
}

template<int MODE>
__global__ void __launch_bounds__(256, 1) gemm_i8(
    const int8_t* __restrict__ Ad1, const int8_t* __restrict__ Ad2,
    const int8_t* __restrict__ Bd1, const int8_t* __restrict__ Bd2,
    const float* __restrict__ sA, const float* __restrict__ sB,
    int K, float* __restrict__ dst, int ldDst)
{
    extern __shared__ __align__(128) char smem[];
    uint32_t sb = smem_u32(smem);
    int rowBase = blockIdx.y * BM, colBase = blockIdx.x * BN;
    int lane = threadIdx.x & 31, wid = threadIdx.x >> 5;
    int wm = wid >> 2, wn = wid & 3;

    int accHi[4][4][4], accMid[4][4][4];
#pragma unroll
    for (int a = 0; a < 4; a++)
#pragma unroll
        for (int b = 0; b < 4; b++)
#pragma unroll
            for (int c = 0; c < 4; c++) { accHi[a][b][c] = 0; accMid[a][b][c] = 0; }

    int nt = K / BK;
    load_stage_i8(sb, Ad1, Ad2, Bd1, Bd2, rowBase, colBase, K, 0);
    cp_commit();
    if (nt > 1)
        load_stage_i8(sb + STAGE_B, Ad1, Ad2, Bd1, Bd2, rowBase, colBase, K, BK);
    cp_commit();

    for (int it = 0; it < nt; it++) {
        cp_wait1();
        __syncthreads();
        if (it + 2 < nt)
            load_stage_i8(sb + ((it + 2) % NSTAGE) * STAGE_B,
                          Ad1, Ad2, Bd1, Bd2, rowBase, colBase, K, (it + 2) * BK);
        cp_commit();
        compute_stage_i8(sb + (it % NSTAGE) * STAGE_B, accHi, accMid, wm, wn, lane);
        __syncthreads();
    }

    // Epilogue: val = sA[r] * sB[c] * (hi + mid/128) / 16129
    const float k1 = 1.0f / 16129.0f, k2 = 1.0f / 128.0f;
#pragma unroll
    for (int mi = 0; mi < 4; mi++) {
        int r0 = rowBase + wm * 64 + mi * 16 + (lane >> 2);
        float sr0 = sA[r0] * k1, sr1 = sA[r0 + 8] * k1;
#pragma unroll
        for (int ntile = 0; ntile < 4; ntile++) {
            int c0 = colBase + wn * 32 + ntile * 8 + (lane & 3) * 2;
            float sc0 = sB[c0], sc1 = sB[c0 + 1];
            int* hi = accHi[mi][ntile];
            int* md = accMid[mi][ntile];
            float v00 = sr0 * sc0 * ((float)hi[0] + (float)md[0] * k2);
            float v01 = sr0 * sc1 * ((float)hi[1] + (float)md[1] * k2);
            float v10 = sr1 * sc0 * ((float)hi[2] + (float)md[2] * k2);
            float v11 = sr1 * sc1 * ((float)hi[3] + (float)md[3] * k2);
            float* p0 = dst + (size_t)r0 * ldDst + c0;
            float* p1 = dst + (size_t)(r0 + 8) * ldDst + c0;
            if (MODE == 2) {
                float2 o0 = *(float2*)p0, o1 = *(float2*)p1;
                v00 += o0.x; v01 += o0.y; v10 += o1.x; v11 += o1.y;
            }
            *(float2*)p0 = make_float2(v00, v01);
            *(float2*)p1 = make_float2(v10, v11);
        }
    }
}

// ---------------------------------------------------------------------------
// Launch  (ALL device-symbol pointers via cudaGetSymbolAddress — R10's bug was
// passing __device__ symbols directly as kernel args from host code)
// ---------------------------------------------------------------------------
extern "C" void kernel_launch(void* const* d_in, const int* in_sizes, int n_in,
                              void* d_out, int out_size)
{
    const float* x   = (const float*)d_in[0];   // [8192, 4096]
    const float* sel = (const float*)d_in[1];   // [16, 256]
    const float* We  = (const float*)d_in[2];   // [4096, 4096]  (K,N)
    const float* Wc  = (const float*)d_in[3];   // [1024, 4096]  (N,K)
    const float* Wn  = (const float*)d_in[4];   // [4096, 1024]  (N,K)
    float* out = (float*)d_out;                 // [8192, 4096]

    // Resolve every device-symbol pointer properly.
    int8_t *ad1, *ad2, *md1, *md2, *wtd1, *wtd2, *wcd1, *wcd2, *wnd1, *wnd2, *cd1, *cd2;
    float *c1f, *s_a, *s_m, *s_c1, *t_we, *t_wc, *t_wn;
    cudaGetSymbolAddress((void**)&ad1,  g_ad1);
    cudaGetSymbolAddress((void**)&ad2,  g_ad2);
    cudaGetSymbolAddress((void**)&md1,  g_md1);
    cudaGetSymbolAddress((void**)&md2,  g_md2);
    cudaGetSymbolAddress((void**)&wtd1, g_wtd1);
    cudaGetSymbolAddress((void**)&wtd2, g_wtd2);
    cudaGetSymbolAddress((void**)&wcd1, g_wcd1);
    cudaGetSymbolAddress((void**)&wcd2, g_wcd2);
    cudaGetSymbolAddress((void**)&wnd1, g_wnd1);
    cudaGetSymbolAddress((void**)&wnd2, g_wnd2);
    cudaGetSymbolAddress((void**)&cd1,  g_c1d1);
    cudaGetSymbolAddress((void**)&cd2,  g_c1d2);
    cudaGetSymbolAddress((void**)&c1f,  g_c1f);
    cudaGetSymbolAddress((void**)&s_a,  g_s_a);
    cudaGetSymbolAddress((void**)&s_m,  g_s_m);
    cudaGetSymbolAddress((void**)&s_c1, g_s_c1);
    cudaGetSymbolAddress((void**)&t_we, g_t_we);
    cudaGetSymbolAddress((void**)&t_wc, g_t_wc);
    cudaGetSymbolAddress((void**)&t_wn, g_t_wn);

    cudaFuncSetAttribute(gemm_i8<0>, cudaFuncAttributeMaxDynamicSharedMemorySize, SMEM_DYN);
    cudaFuncSetAttribute(gemm_i8<1>, cudaFuncAttributeMaxDynamicSharedMemorySize, SMEM_DYN);
    cudaFuncSetAttribute(gemm_i8<2>, cudaFuncAttributeMaxDynamicSharedMemorySize, SMEM_DYN);

    // gating + quantization prep
    gating_kernel<<<B_ROWS, 512>>>(x, sel);
    quant_am<<<B_ROWS, 256>>>(x);
    zero_twe<<<OUT_F / 256, 256>>>();
    colmax_we<<<IN_F / 64, 256>>>(We);
    quant_weT<<<dim3(OUT_F / 32, IN_F / 32), dim3(32, 8)>>>(We);
    quant_rows<<<COMP, 256>>>(Wc, IN_F, wcd1, wcd2, t_wc);
    quant_rows<<<OUT_F, 256>>>(Wn, COMP, wnd1, wnd2, t_wn);

    // compress GEMM: c1f = m . Wc^T   [8192, 1024]
    gemm_i8<0><<<dim3(COMP / BN, B_ROWS / BM), 256, SMEM_DYN>>>(
        md1, md2, wcd1, wcd2, s_m, t_wc, IN_F, c1f, COMP);

    // quantize c1
    quant_rows<<<B_ROWS, 256>>>(c1f, COMP, cd1, cd2, s_c1);

    // expert GEMM: out = a . WeT^T   [8192, 4096]
    gemm_i8<1><<<dim3(OUT_F / BN, B_ROWS / BM), 256, SMEM_DYN>>>(
        ad1, ad2, wtd1, wtd2, s_a, t_we, IN_F, out, OUT_F);

    // net GEMM: out += c1 . Wn^T
    gemm_i8<2><<<dim3(OUT_F / BN, B_ROWS / BM), 256, SMEM_DYN>>>(
        cd1, cd2, wnd1, wnd2, s_c1, t_wn, COMP, out, OUT_F);
}

// round 13
// speedup vs baseline: 2.6687x; 2.6687x over previous
#include <cuda_runtime.h>
#include <cuda_fp16.h>
#include <cstdint>
#include <math.h>

// ---------------------------------------------------------------------------
// Problem constants
// ---------------------------------------------------------------------------
#define B_ROWS 8192
#define IN_F   4096
#define OUT_F  4096
#define NFRAG  16
#define FS     256
#define COMP   1024

// GEMM tiling
#define BM 128
#define BN 128
#define BK 32            // fp16 elements per stage (64 bytes per row)
#define NSTAGE 3

#define TILE_B  (128 * 64)                 // one 128x32 fp16 tile = 8 KB
#define STAGE_B (3 * TILE_B)               // A, Bh, Bl = 24 KB
#define SMEM_DYN (NSTAGE * STAGE_B)        // 72 KB  (2 CTAs/SM: 144 <= 227 KB)

// swizzle: 64B rows, 4x16B chunks; chunk ^= (row>>1)&3  (conflict-free LDSM)
#define SWZ(r, c) ((((c) ^ (((r) >> 1) & 3)) << 4))

// ---------------------------------------------------------------------------
// Scratch (static device globals; no runtime allocation)
// ---------------------------------------------------------------------------
__device__ float g_probs[B_ROWS * NFRAG];

__device__ __align__(16) __half g_af [B_ROWS * IN_F];   // fp16(x * p)
__device__ __align__(16) __half g_mf [B_ROWS * IN_F];   // fp16(x - x*p)
__device__ __align__(16) __half g_wth[OUT_F * IN_F];    // We^T hi  [N,K]
__device__ __align__(16) __half g_wtl[OUT_F * IN_F];    // We^T lo
__device__ __align__(16) __half g_wch[COMP * IN_F];     // Wc hi [N,K]
__device__ __align__(16) __half g_wcl[COMP * IN_F];     // Wc lo
__device__ __align__(16) __half g_wnh[OUT_F * COMP];    // Wn hi [N,K]
__device__ __align__(16) __half g_wnl[OUT_F * COMP];    // Wn lo
__device__ __align__(16) __half g_c1f[B_ROWS * COMP];   // fp16 compressed

// ---------------------------------------------------------------------------
// Helpers (family-safe PTX only: cp.async, ldmatrix, fp16 mma.sync)
// ---------------------------------------------------------------------------
__device__ __forceinline__ uint32_t smem_u32(const void* p) {
    uint32_t a;
    asm("{ .reg .u64 t; cvta.to.shared.u64 t, %1; cvt.u32.u64 %0, t; }"
        : "=r"(a) : "l"(p));
    return a;
}
__device__ __forceinline__ void cp16(uint32_t dst, const void* src) {
    asm volatile("cp.async.cg.shared.global [%0], [%1], 16;" :: "r"(dst), "l"(src));
}
__device__ __forceinline__ void cp_commit() {
    asm volatile("cp.async.commit_group;");
}
__device__ __forceinline__ void cp_wait1() {
    asm volatile("cp.async.wait_group 1;" ::: "memory");
}
__device__ __forceinline__ void ldsm4(uint32_t* f, uint32_t a) {
    asm volatile("ldmatrix.sync.aligned.m8n8.x4.shared.b16 {%0,%1,%2,%3}, [%4];"
                 : "=r"(f[0]), "=r"(f[1]), "=r"(f[2]), "=r"(f[3]) : "r"(a));
}
__device__ __forceinline__ void hmma(float* d, const uint32_t* a,
                                     uint32_t b0, uint32_t b1) {
    asm volatile(
        "mma.sync.aligned.m16n8k16.row.col.f32.f16.f16.f32 "
        "{%0,%1,%2,%3}, {%4,%5,%6,%7}, {%8,%9}, {%0,%1,%2,%3};"
        : "+f"(d[0]), "+f"(d[1]), "+f"(d[2]), "+f"(d[3])
        : "r"(a[0]), "r"(a[1]), "r"(a[2]), "r"(a[3]), "r"(b0), "r"(b1));
}
// fp16 hi/lo split (lo may be subnormal; fine — it's a small correction term)
__device__ __forceinline__ void hsplit(float f, __half& h, __half& l) {
    h = __float2half_rn(f);
    l = __float2half_rn(f - __half2float(h));
}
union PackH4 { __half h[4]; uint2 u; };

// ---------------------------------------------------------------------------
// Gating: softmax over fragment scores
// ---------------------------------------------------------------------------
__global__ void __launch_bounds__(512) gating_kernel(
    const float* __restrict__ x, const float* __restrict__ sel)
{
    int b = blockIdx.x, t = threadIdx.x;
    int w = t >> 5, lane = t & 31;
    const float* xr = x + (size_t)b * IN_F + w * FS;
    const float* sr = sel + w * FS;
    float acc = 0.f;
#pragma unroll
    for (int j = 0; j < 8; j++) acc += xr[lane + 32*j] * sr[lane + 32*j];
#pragma unroll
    for (int o = 16; o; o >>= 1) acc += __shfl_xor_sync(0xFFFFFFFFu, acc, o);
    __shared__ float s[NFRAG];
    if (lane == 0) s[w] = acc;
    __syncthreads();
    if (t < NFRAG) {
        float m = -INFINITY;
#pragma unroll
        for (int f = 0; f < NFRAG; f++) m = fmaxf(m, s[f]);
        float sum = 0.f;
#pragma unroll
        for (int f = 0; f < NFRAG; f++) sum += __expf(s[f] - m);
        g_probs[b * NFRAG + t] = __expf(s[t] - m) / sum;
    }
}

// ---------------------------------------------------------------------------
// Prescale: a = x*p, m = x - a; round both to fp16
// ---------------------------------------------------------------------------
__global__ void __launch_bounds__(256) prescale_f16(const float* __restrict__ x)
{
    size_t base = ((size_t)blockIdx.x * blockDim.x + threadIdx.x) * 4;
    int b   = (int)(base >> 12);
    int col = (int)(base & 4095);
    float p = g_probs[b * NFRAG + (col >> 8)];
    float4 v = *(const float4*)(x + base);
    float a0 = v.x*p, a1 = v.y*p, a2 = v.z*p, a3 = v.w*p;
    PackH4 af, mf;
    af.h[0] = __float2half_rn(a0);      af.h[1] = __float2half_rn(a1);
    af.h[2] = __float2half_rn(a2);      af.h[3] = __float2half_rn(a3);
    mf.h[0] = __float2half_rn(v.x-a0);  mf.h[1] = __float2half_rn(v.y-a1);
    mf.h[2] = __float2half_rn(v.z-a2);  mf.h[3] = __float2half_rn(v.w-a3);
    *(uint2*)(g_af + base) = af.u;
    *(uint2*)(g_mf + base) = mf.u;
}

// ---------------------------------------------------------------------------
// Transpose + split We [K,N] -> WeT [N,K] fp16 hi/lo
// ---------------------------------------------------------------------------
__global__ void __launch_bounds__(256) transpose_split_we(const float* __restrict__ We)
{
    __shared__ float tile[32][33];
    int k0 = blockIdx.y * 32, n0 = blockIdx.x * 32;
    int tx = threadIdx.x, ty = threadIdx.y;
#pragma unroll
    for (int r = 0; r < 4; r++)
        tile[ty + r*8][tx] = We[(size_t)(k0 + ty + r*8) * OUT_F + n0 + tx];
    __syncthreads();
#pragma unroll
    for (int r = 0; r < 4; r++) {
        __half h, l;
        hsplit(tile[tx][ty + r*8], h, l);
        size_t o = (size_t)(n0 + ty + r*8) * IN_F + k0 + tx;
        g_wth[o] = h;
        g_wtl[o] = l;
    }
}

// ---------------------------------------------------------------------------
// Generic split (Wc / Wn) — already [N,K] K-contiguous
// ---------------------------------------------------------------------------
__global__ void __launch_bounds__(256) split_generic(
    const float* __restrict__ src, __half* __restrict__ hp, __half* __restrict__ lp)
{
    size_t base = ((size_t)blockIdx.x * blockDim.x + threadIdx.x) * 4;
    float4 v = *(const float4*)(src + base);
    PackH4 h, l;
    hsplit(v.x, h.h[0], l.h[0]); hsplit(v.y, h.h[1], l.h[1]);
    hsplit(v.z, h.h[2], l.h[2]); hsplit(v.w, h.h[3], l.h[3]);
    *(uint2*)(hp + base) = h.u;
    *(uint2*)(lp + base) = l.u;
}

// ---------------------------------------------------------------------------
// GEMM core: C = A_f16 . (Bh + Bl)^T   (2 MMA products per k16)
// ---------------------------------------------------------------------------
struct SegP {
    const __half *A, *Bh, *Bl;
    int ldA, ldB, nt;    // nt = number of BK tiles in this segment
};

// stage load: A 128x32, Bh/Bl 128x32, swizzled (6 cp16 per thread)
__device__ __forceinline__ void load_stage(uint32_t st, const SegP& sg,
                                           int rowBase, int colBase, int kt)
{
    int t = threadIdx.x;
#pragma unroll
    for (int i = 0; i < 2; i++) {
        int id = t + i * 256;
        int r  = id >> 2;
        int c  = id & 3;
        uint32_t off = (uint32_t)(r * 64 + SWZ(r, c));
        size_t ga = (size_t)(rowBase + r) * sg.ldA + kt + c * 8;
        size_t gb = (size_t)(colBase + r) * sg.ldB + kt + c * 8;
        cp16(st + off,              sg.A  + ga);
        cp16(st + TILE_B + off,     sg.Bh + gb);
        cp16(st + 2 * TILE_B + off, sg.Bl + gb);
    }
}

// compute one BK=32 stage: acc += A.(Bh)^T + A.(Bl)^T
__device__ __forceinline__ void compute_stage(uint32_t st, float acc[4][4][4],
                                              int wm, int wn, int lane)
{
#pragma unroll
    for (int kk = 0; kk < 2; kk++) {                 // k sub-steps of 16
        int cbase = kk * 2 + (lane >> 4);            // 16B chunk index (0..3)
        uint32_t af[4][4];
#pragma unroll
        for (int mi = 0; mi < 4; mi++) {
            int r = wm * 64 + mi * 16 + (lane & 15);
            uint32_t off = (uint32_t)(r * 64 + SWZ(r, cbase));
            ldsm4(af[mi], st + off);
        }
        uint32_t bh[2][4], bl[2][4];
#pragma unroll
        for (int ni = 0; ni < 2; ni++) {
            int r = wn * 32 + ni * 16 + (lane & 15);
            uint32_t off = (uint32_t)(r * 64 + SWZ(r, cbase));
            ldsm4(bh[ni], st + TILE_B + off);
            ldsm4(bl[ni], st + 2 * TILE_B + off);
        }
#pragma unroll
        for (int mi = 0; mi < 4; mi++)
#pragma unroll
            for (int g = 0; g < 4; g++) {
                int ni = g >> 1, s = g & 1;
                hmma(acc[mi][g], af[mi], bh[ni][s], bh[ni][s + 2]);
                hmma(acc[mi][g], af[mi], bl[ni][s], bl[ni][s + 2]);
            }
    }
}

// pipelined mainloop over (up to 2) segments; fills acc
__device__ __forceinline__ void run_mainloop(uint32_t sb, const SegP* segs, int nseg,
                                             int rowBase, int colBase,
                                             float acc[4][4][4])
{
    int lane = threadIdx.x & 31, wid = threadIdx.x >> 5;
    int wm = wid >> 2, wn = wid & 3;

    int ntTot = 0;
    for (int s = 0; s < nseg; s++) ntTot += segs[s].nt;

    auto issue = [&](int tile, int stageIdx) {
        int i = tile, s = 0;
        while (s < nseg - 1 && i >= segs[s].nt) { i -= segs[s].nt; s++; }
        load_stage(sb + stageIdx * STAGE_B, segs[s], rowBase, colBase, i * BK);
    };

    issue(0, 0); cp_commit();
    if (ntTot > 1) issue(1, 1);
    cp_commit();

    for (int it = 0; it < ntTot; it++) {
        cp_wait1();
        __syncthreads();
        if (it + 2 < ntTot) issue(it + 2, (it + 2) % NSTAGE);
        cp_commit();
        compute_stage(sb + (it % NSTAGE) * STAGE_B, acc, wm, wn, lane);
        __syncthreads();
    }
}

// ---------------------------------------------------------------------------
// GEMM 1: c1 = m . Wc^T  -> fp16
// ---------------------------------------------------------------------------
__global__ void __launch_bounds__(256, 2) gemm_compress_h(void)
{
    extern __shared__ __align__(128) char smem[];
    uint32_t sb = smem_u32(smem);
    int rowBase = blockIdx.y * BM, colBase = blockIdx.x * BN;

    float acc[4][4][4];
#pragma unroll
    for (int a = 0; a < 4; a++)
#pragma unroll
        for (int b = 0; b < 4; b++)
#pragma unroll
            for (int c = 0; c < 4; c++) acc[a][b][c] = 0.f;

    SegP segs[1] = { { g_mf, g_wch, g_wcl, IN_F, IN_F, IN_F / BK } };
    run_mainloop(sb, segs, 1, rowBase, colBase, acc);

    int lane = threadIdx.x & 31, wid = threadIdx.x >> 5;
    int wm = wid >> 2, wn = wid & 3;
#pragma unroll
    for (int mi = 0; mi < 4; mi++)
#pragma unroll
        for (int g = 0; g < 4; g++) {
            int r0 = rowBase + wm * 64 + mi * 16 + (lane >> 2);
            int c0 = colBase + wn * 32 + g * 8 + (lane & 3) * 2;
            __half2 v0 = __floats2half2_rn(acc[mi][g][0], acc[mi][g][1]);
            __half2 v1 = __floats2half2_rn(acc[mi][g][2], acc[mi][g][3]);
            *(__half2*)(g_c1f + (size_t)r0 * COMP + c0)       = v0;
            *(__half2*)(g_c1f + (size_t)(r0 + 8) * COMP + c0) = v1;
        }
}

// ---------------------------------------------------------------------------
// GEMM 2 (fused): out = a . We  +  c1 . Wn^T
// ---------------------------------------------------------------------------
__global__ void __launch_bounds__(256, 2) gemm_out_h(float* __restrict__ out)
{
    extern __shared__ __align__(128) char smem[];
    uint32_t sb = smem_u32(smem);
    int rowBase = blockIdx.y * BM, colBase = blockIdx.x * BN;

    float acc[4][4][4];
#pragma unroll
    for (int a = 0; a < 4; a++)
#pragma unroll
        for (int b = 0; b < 4; b++)
#pragma unroll
            for (int c = 0; c < 4; c++) acc[a][b][c] = 0.f;

    SegP segs[2] = {
        { g_af,  g_wth, g_wtl, IN_F, IN_F, IN_F / BK },
        { g_c1f, g_wnh, g_wnl, COMP, COMP, COMP / BK },
    };
    run_mainloop(sb, segs, 2, rowBase, colBase, acc);

    int lane = threadIdx.x & 31, wid = threadIdx.x >> 5;
    int wm = wid >> 2, wn = wid & 3;
#pragma unroll
    for (int mi = 0; mi < 4; mi++)
#pragma unroll
        for (int g = 0; g < 4; g++) {
            int r0 = rowBase + wm * 64 + mi * 16 + (lane >> 2);
            int c0 = colBase + wn * 32 + g * 8 + (lane & 3) * 2;
            *(float2*)(out + (size_t)r0 * OUT_F + c0) =
                make_float2(acc[mi][g][0], acc[mi][g][1]);
            *(float2*)(out + (size_t)(r0 + 8) * OUT_F + c0) =
                make_float2(acc[mi][g][2], acc[mi][g][3]);
        }
}

// ---------------------------------------------------------------------------
// Launch  (host-passed device-symbol pointers resolved via cudaGetSymbolAddress)
// ---------------------------------------------------------------------------
extern "C" void kernel_launch(void* const* d_in, const int* in_sizes, int n_in,
                              void* d_out, int out_size)
{
    const float* x   = (const float*)d_in[0];   // [8192, 4096]
    const float* sel = (const float*)d_in[1];   // [16, 256]
    const float* We  = (const float*)d_in[2];   // [4096, 4096]  (K,N)
    const float* Wc  = (const float*)d_in[3];   // [1024, 4096]  (N,K)
    const float* Wn  = (const float*)d_in[4];   // [4096, 1024]  (N,K)
    float* out = (float*)d_out;                 // [8192, 4096]

    __half *wch, *wcl, *wnh, *wnl;
    cudaGetSymbolAddress((void**)&wch, g_wch);
    cudaGetSymbolAddress((void**)&wcl, g_wcl);
    cudaGetSymbolAddress((void**)&wnh, g_wnh);
    cudaGetSymbolAddress((void**)&wnl, g_wnl);

    cudaFuncSetAttribute(gemm_compress_h, cudaFuncAttributeMaxDynamicSharedMemorySize, SMEM_DYN);
    cudaFuncSetAttribute(gemm_out_h,      cudaFuncAttributeMaxDynamicSharedMemorySize, SMEM_DYN);

    gating_kernel<<<B_ROWS, 512>>>(x, sel);
    prescale_f16<<<(B_ROWS * (IN_F / 4)) / 256, 256>>>(x);
    transpose_split_we<<<dim3(OUT_F / 32, IN_F / 32), dim3(32, 8)>>>(We);
    split_generic<<<(COMP * (IN_F / 4)) / 256, 256>>>(Wc, wch, wcl);
    split_generic<<<(OUT_F * (COMP / 4)) / 256, 256>>>(Wn, wnh, wnl);

    gemm_compress_h<<<dim3(COMP / BN, B_ROWS / BM), 256, SMEM_DYN>>>();
    gemm_out_h<<<dim3(OUT_F / BN, B_ROWS / BM), 256, SMEM_DYN>>>(out);
}

// round 15
// speedup vs baseline: 2.9436x; 1.1030x over previous
#include <cuda_runtime.h>
#include <cuda_fp16.h>
#include <cstdint>
#include <math.h>

// ---------------------------------------------------------------------------
// Problem constants
// ---------------------------------------------------------------------------
#define B_ROWS 8192
#define IN_F   4096
#define OUT_F  4096
#define NFRAG  16
#define FS     256
#define COMP   1024

// GEMM tiling
#define BM 128
#define BN 128
#define BK 32            // fp16 elements per stage (64 bytes per row)
#define NSTAGE 3

#define TILE_B  (128 * 64)                 // one 128x32 fp16 tile = 8 KB
#define STAGE_B (3 * TILE_B)               // A, Bh, (Bl) = 24 KB slot
#define SMEM_DYN (NSTAGE * STAGE_B)        // 72 KB  (2 CTAs/SM: 144 <= 228 KB)

// swizzle: 64B rows, 4x16B chunks; chunk ^= (row>>1)&3  (conflict-free LDSM)
#define SWZ(r, c) ((((c) ^ (((r) >> 1) & 3)) << 4))

// ---------------------------------------------------------------------------
// Scratch (static device globals; no runtime allocation)
// ---------------------------------------------------------------------------
__device__ float g_probs[B_ROWS * NFRAG];

__device__ __align__(16) __half g_af [B_ROWS * IN_F];   // fp16(x * p)
__device__ __align__(16) __half g_mf [B_ROWS * IN_F];   // fp16(x - x*p)
__device__ __align__(16) __half g_wth[OUT_F * IN_F];    // We^T  [N,K] (single fp16)
__device__ __align__(16) __half g_wch[COMP * IN_F];     // Wc hi [N,K]
__device__ __align__(16) __half g_wcl[COMP * IN_F];     // Wc lo
__device__ __align__(16) __half g_wnh[OUT_F * COMP];    // Wn hi [N,K]
__device__ __align__(16) __half g_wnl[OUT_F * COMP];    // Wn lo
__device__ __align__(16) __half g_c1f[B_ROWS * COMP];   // fp16 compressed

// ---------------------------------------------------------------------------
// Helpers (family-safe PTX only: cp.async, ldmatrix, fp16 mma.sync)
// ---------------------------------------------------------------------------
__device__ __forceinline__ uint32_t smem_u32(const void* p) {
    uint32_t a;
    asm("{ .reg .u64 t; cvta.to.shared.u64 t, %1; cvt.u32.u64 %0, t; }"
        : "=r"(a) : "l"(p));
    return a;
}
__device__ __forceinline__ void cp16(uint32_t dst, const void* src) {
    asm volatile("cp.async.cg.shared.global [%0], [%1], 16;" :: "r"(dst), "l"(src));
}
__device__ __forceinline__ void cp_commit() {
    asm volatile("cp.async.commit_group;");
}
__device__ __forceinline__ void cp_wait1() {
    asm volatile("cp.async.wait_group 1;" ::: "memory");
}
__device__ __forceinline__ void ldsm4(uint32_t* f, uint32_t a) {
    asm volatile("ldmatrix.sync.aligned.m8n8.x4.shared.b16 {%0,%1,%2,%3}, [%4];"
                 : "=r"(f[0]), "=r"(f[1]), "=r"(f[2]), "=r"(f[3]) : "r"(a));
}
__device__ __forceinline__ void hmma(float* d, const uint32_t* a,
                                     uint32_t b0, uint32_t b1) {
    asm volatile(
        "mma.sync.aligned.m16n8k16.row.col.f32.f16.f16.f32 "
        "{%0,%1,%2,%3}, {%4,%5,%6,%7}, {%8,%9}, {%0,%1,%2,%3};"
        : "+f"(d[0]), "+f"(d[1]), "+f"(d[2]), "+f"(d[3])
        : "r"(a[0]), "r"(a[1]), "r"(a[2]), "r"(a[3]), "r"(b0), "r"(b1));
}
// fp16 hi/lo split (lo may be subnormal; fine — small correction term)
__device__ __forceinline__ void hsplit(float f, __half& h, __half& l) {
    h = __float2half_rn(f);
    l = __float2half_rn(f - __half2float(h));
}
union PackH4 { __half h[4]; uint2 u; };

// ---------------------------------------------------------------------------
// Gating: softmax over fragment scores
// ---------------------------------------------------------------------------
__global__ void __launch_bounds__(512) gating_kernel(
    const float* __restrict__ x, const float* __restrict__ sel)
{
    int b = blockIdx.x, t = threadIdx.x;
    int w = t >> 5, lane = t & 31;
    const float* xr = x + (size_t)b * IN_F + w * FS;
    const float* sr = sel + w * FS;
    float acc = 0.f;
#pragma unroll
    for (int j = 0; j < 8; j++) acc += xr[lane + 32*j] * sr[lane + 32*j];
#pragma unroll
    for (int o = 16; o; o >>= 1) acc += __shfl_xor_sync(0xFFFFFFFFu, acc, o);
    __shared__ float s[NFRAG];
    if (lane == 0) s[w] = acc;
    __syncthreads();
    if (t < NFRAG) {
        float m = -INFINITY;
#pragma unroll
        for (int f = 0; f < NFRAG; f++) m = fmaxf(m, s[f]);
        float sum = 0.f;
#pragma unroll
        for (int f = 0; f < NFRAG; f++) sum += __expf(s[f] - m);
        g_probs[b * NFRAG + t] = __expf(s[t] - m) / sum;
    }
}

// ---------------------------------------------------------------------------
// Prescale: a = x*p, m = x - a; round both to fp16
// ---------------------------------------------------------------------------
__global__ void __launch_bounds__(256) prescale_f16(const float* __restrict__ x)
{
    size_t base = ((size_t)blockIdx.x * blockDim.x + threadIdx.x) * 4;
    int b   = (int)(base >> 12);
    int col = (int)(base & 4095);
    float p = g_probs[b * NFRAG + (col >> 8)];
    float4 v = *(const float4*)(x + base);
    float a0 = v.x*p, a1 = v.y*p, a2 = v.z*p, a3 = v.w*p;
    PackH4 af, mf;
    af.h[0] = __float2half_rn(a0);      af.h[1] = __float2half_rn(a1);
    af.h[2] = __float2half_rn(a2);      af.h[3] = __float2half_rn(a3);
    mf.h[0] = __float2half_rn(v.x-a0);  mf.h[1] = __float2half_rn(v.y-a1);
    mf.h[2] = __float2half_rn(v.z-a2);  mf.h[3] = __float2half_rn(v.w-a3);
    *(uint2*)(g_af + base) = af.u;
    *(uint2*)(g_mf + base) = mf.u;
}

// ---------------------------------------------------------------------------
// Transpose We [K,N] -> WeT [N,K], single fp16 (expert path = 1 product)
// ---------------------------------------------------------------------------
__global__ void __launch_bounds__(256) transpose_we(const float* __restrict__ We)
{
    __shared__ float tile[32][33];
    int k0 = blockIdx.y * 32, n0 = blockIdx.x * 32;
    int tx = threadIdx.x, ty = threadIdx.y;
#pragma unroll
    for (int r = 0; r < 4; r++)
        tile[ty + r*8][tx] = We[(size_t)(k0 + ty + r*8) * OUT_F + n0 + tx];
    __syncthreads();
#pragma unroll
    for (int r = 0; r < 4; r++) {
        size_t o = (size_t)(n0 + ty + r*8) * IN_F + k0 + tx;
        g_wth[o] = __float2half_rn(tile[tx][ty + r*8]);
    }
}

// ---------------------------------------------------------------------------
// Generic split (Wc / Wn) — already [N,K] K-contiguous
// ---------------------------------------------------------------------------
__global__ void __launch_bounds__(256) split_generic(
    const float* __restrict__ src, __half* __restrict__ hp, __half* __restrict__ lp)
{
    size_t base = ((size_t)blockIdx.x * blockDim.x + threadIdx.x) * 4;
    float4 v = *(const float4*)(src + base);
    PackH4 h, l;
    hsplit(v.x, h.h[0], l.h[0]); hsplit(v.y, h.h[1], l.h[1]);
    hsplit(v.z, h.h[2], l.h[2]); hsplit(v.w, h.h[3], l.h[3]);
    *(uint2*)(hp + base) = h.u;
    *(uint2*)(lp + base) = l.u;
}

// ---------------------------------------------------------------------------
// GEMM core: C = A_f16 . (Bh [+ Bl])^T   (1 or 2 MMA products per k16)
// ---------------------------------------------------------------------------
struct SegP {
    const __half *A, *Bh, *Bl;   // Bl == nullptr -> single product
    int ldA, ldB, nt;            // nt = number of BK tiles in this segment
    int dual;                    // 1: load Bl + second product
};

// stage load: A 128x32, Bh (and Bl if dual) 128x32, swizzled
__device__ __forceinline__ void load_stage(uint32_t st, const SegP& sg,
                                           int rowBase, int colBase, int kt)
{
    int t = threadIdx.x;
#pragma unroll
    for (int i = 0; i < 2; i++) {
        int id = t + i * 256;
        int r  = id >> 2;
        int c  = id & 3;
        uint32_t off = (uint32_t)(r * 64 + SWZ(r, c));
        size_t ga = (size_t)(rowBase + r) * sg.ldA + kt + c * 8;
        size_t gb = (size_t)(colBase + r) * sg.ldB + kt + c * 8;
        cp16(st + off,          sg.A  + ga);
        cp16(st + TILE_B + off, sg.Bh + gb);
        if (sg.dual)
            cp16(st + 2 * TILE_B + off, sg.Bl + gb);
    }
}

// compute one BK=32 stage
__device__ __forceinline__ void compute_stage(uint32_t st, float acc[4][4][4],
                                              int wm, int wn, int lane, int dual)
{
#pragma unroll
    for (int kk = 0; kk < 2; kk++) {                 // k sub-steps of 16
        int cbase = kk * 2 + (lane >> 4);            // 16B chunk index (0..3)
        uint32_t af[4][4];
#pragma unroll
        for (int mi = 0; mi < 4; mi++) {
            int r = wm * 64 + mi * 16 + (lane & 15);
            uint32_t off = (uint32_t)(r * 64 + SWZ(r, cbase));
            ldsm4(af[mi], st + off);
        }
        uint32_t bh[2][4], bl[2][4];
#pragma unroll
        for (int ni = 0; ni < 2; ni++) {
            int r = wn * 32 + ni * 16 + (lane & 15);
            uint32_t off = (uint32_t)(r * 64 + SWZ(r, cbase));
            ldsm4(bh[ni], st + TILE_B + off);
            if (dual) ldsm4(bl[ni], st + 2 * TILE_B + off);
        }
#pragma unroll
        for (int mi = 0; mi < 4; mi++)
#pragma unroll
            for (int g = 0; g < 4; g++) {
                int ni = g >> 1, s = g & 1;
                hmma(acc[mi][g], af[mi], bh[ni][s], bh[ni][s + 2]);
                if (dual)
                    hmma(acc[mi][g], af[mi], bl[ni][s], bl[ni][s + 2]);
            }
    }
}

// pipelined mainloop over (up to 2) segments; fills acc
__device__ __forceinline__ void run_mainloop(uint32_t sb, const SegP* segs, int nseg,
                                             int rowBase, int colBase,
                                             float acc[4][4][4])
{
    int lane = threadIdx.x & 31, wid = threadIdx.x >> 5;
    int wm = wid >> 2, wn = wid & 3;

    int ntTot = 0;
    for (int s = 0; s < nseg; s++) ntTot += segs[s].nt;

    auto segOf = [&](int tile, int& local) {
        int i = tile, s = 0;
        while (s < nseg - 1 && i >= segs[s].nt) { i -= segs[s].nt; s++; }
        local = i;
        return s;
    };
    auto issue = [&](int tile, int stageIdx) {
        int i; int s = segOf(tile, i);
        load_stage(sb + stageIdx * STAGE_B, segs[s], rowBase, colBase, i * BK);
    };

    issue(0, 0); cp_commit();
    if (ntTot > 1) issue(1, 1);
    cp_commit();

    for (int it = 0; it < ntTot; it++) {
        cp_wait1();
        __syncthreads();
        if (it + 2 < ntTot) issue(it + 2, (it + 2) % NSTAGE);
        cp_commit();
        int li; int s = segOf(it, li);
        compute_stage(sb + (it % NSTAGE) * STAGE_B, acc, wm, wn, lane, segs[s].dual);
        __syncthreads();
    }
}

// ---------------------------------------------------------------------------
// GEMM 1: c1 = m . Wc^T  -> fp16   (dual product)
// ---------------------------------------------------------------------------
__global__ void __launch_bounds__(256, 2) gemm_compress_h(void)
{
    extern __shared__ __align__(128) char smem[];
    uint32_t sb = smem_u32(smem);
    int rowBase = blockIdx.y * BM, colBase = blockIdx.x * BN;

    float acc[4][4][4];
#pragma unroll
    for (int a = 0; a < 4; a++)
#pragma unroll
        for (int b = 0; b < 4; b++)
#pragma unroll
            for (int c = 0; c < 4; c++) acc[a][b][c] = 0.f;

    SegP segs[1] = { { g_mf, g_wch, g_wcl, IN_F, IN_F, IN_F / BK, 1 } };
    run_mainloop(sb, segs, 1, rowBase, colBase, acc);

    int lane = threadIdx.x & 31, wid = threadIdx.x >> 5;
    int wm = wid >> 2, wn = wid & 3;
#pragma unroll
    for (int mi = 0; mi < 4; mi++)
#pragma unroll
        for (int g = 0; g < 4; g++) {
            int r0 = rowBase + wm * 64 + mi * 16 + (lane >> 2);
            int c0 = colBase + wn * 32 + g * 8 + (lane & 3) * 2;
            __half2 v0 = __floats2half2_rn(acc[mi][g][0], acc[mi][g][1]);
            __half2 v1 = __floats2half2_rn(acc[mi][g][2], acc[mi][g][3]);
            *(__half2*)(g_c1f + (size_t)r0 * COMP + c0)       = v0;
            *(__half2*)(g_c1f + (size_t)(r0 + 8) * COMP + c0) = v1;
        }
}

// ---------------------------------------------------------------------------
// GEMM 2 (fused): out = a . We (single product)  +  c1 . Wn^T (dual)
// ---------------------------------------------------------------------------
__global__ void __launch_bounds__(256, 2) gemm_out_h(float* __restrict__ out)
{
    extern __shared__ __align__(128) char smem[];
    uint32_t sb = smem_u32(smem);
    int rowBase = blockIdx.y * BM, colBase = blockIdx.x * BN;

    float acc[4][4][4];
#pragma unroll
    for (int a = 0; a < 4; a++)
#pragma unroll
        for (int b = 0; b < 4; b++)
#pragma unroll
            for (int c = 0; c < 4; c++) acc[a][b][c] = 0.f;

    SegP segs[2] = {
        { g_af,  g_wth, (const __half*)0, IN_F, IN_F, IN_F / BK, 0 },
        { g_c1f, g_wnh, g_wnl,            COMP, COMP, COMP / BK, 1 },
    };
    run_mainloop(sb, segs, 2, rowBase, colBase, acc);

    int lane = threadIdx.x & 31, wid = threadIdx.x >> 5;
    int wm = wid >> 2, wn = wid & 3;
#pragma unroll
    for (int mi = 0; mi < 4; mi++)
#pragma unroll
        for (int g = 0; g < 4; g++) {
            int r0 = rowBase + wm * 64 + mi * 16 + (lane >> 2);
            int c0 = colBase + wn * 32 + g * 8 + (lane & 3) * 2;
            *(float2*)(out + (size_t)r0 * OUT_F + c0) =
                make_float2(acc[mi][g][0], acc[mi][g][1]);
            *(float2*)(out + (size_t)(r0 + 8) * OUT_F + c0) =
                make_float2(acc[mi][g][2], acc[mi][g][3]);
        }
}

// ---------------------------------------------------------------------------
// Launch
// ---------------------------------------------------------------------------
extern "C" void kernel_launch(void* const* d_in, const int* in_sizes, int n_in,
                              void* d_out, int out_size)
{
    const float* x   = (const float*)d_in[0];   // [8192, 4096]
    const float* sel = (const float*)d_in[1];   // [16, 256]
    const float* We  = (const float*)d_in[2];   // [4096, 4096]  (K,N)
    const float* Wc  = (const float*)d_in[3];   // [1024, 4096]  (N,K)
    const float* Wn  = (const float*)d_in[4];   // [4096, 1024]  (N,K)
    float* out = (float*)d_out;                 // [8192, 4096]

    __half *wch, *wcl, *wnh, *wnl;
    cudaGetSymbolAddress((void**)&wch, g_wch);
    cudaGetSymbolAddress((void**)&wcl, g_wcl);
    cudaGetSymbolAddress((void**)&wnh, g_wnh);
    cudaGetSymbolAddress((void**)&wnl, g_wnl);

    cudaFuncSetAttribute(gemm_compress_h, cudaFuncAttributeMaxDynamicSharedMemorySize, SMEM_DYN);
    cudaFuncSetAttribute(gemm_out_h,      cudaFuncAttributeMaxDynamicSharedMemorySize, SMEM_DYN);

    gating_kernel<<<B_ROWS, 512>>>(x, sel);
    prescale_f16<<<(B_ROWS * (IN_F / 4)) / 256, 256>>>(x);
    transpose_we<<<dim3(OUT_F / 32, IN_F / 32), dim3(32, 8)>>>(We);
    split_generic<<<(COMP * (IN_F / 4)) / 256, 256>>>(Wc, wch, wcl);
    split_generic<<<(OUT_F * (COMP / 4)) / 256, 256>>>(Wn, wnh, wnl);

    gemm_compress_h<<<dim3(COMP / BN, B_ROWS / BM), 256, SMEM_DYN>>>();
    gemm_out_h<<<dim3(OUT_F / BN, B_ROWS / BM), 256, SMEM_DYN>>>(out);
}

// round 16
// speedup vs baseline: 7.6072x; 2.5843x over previous
#include <cuda_runtime.h>
#include <cuda_fp16.h>
#include <cstdint>
#include <math.h>

// ---------------------------------------------------------------------------
// Problem constants
// ---------------------------------------------------------------------------
#define B_ROWS 8192
#define IN_F   4096
#define OUT_F  4096
#define NFRAG  16
#define FS     256
#define COMP   1024

// GEMM tiling
#define BM 128
#define BN 128
#define BK 64            // fp16 elements per stage (128 bytes per row)
#define NSTAGE 3

#define TILE_B  (128 * 128)                // one 128x64 fp16 tile = 16 KB
#define STAGE_B (2 * TILE_B)               // A + B = 32 KB
#define SMEM_DYN (NSTAGE * STAGE_B)        // 96 KB  (2 CTAs/SM: 192 <= 228 KB)

// swizzle: 128B rows, 8x16B chunks; chunk ^= r&7  (conflict-free LDSM + STS)
#define SWZ(r, c) ((((c) ^ ((r) & 7)) << 4))

// ---------------------------------------------------------------------------
// Scratch (static device globals; no runtime allocation)
// ---------------------------------------------------------------------------
__device__ float g_probs[B_ROWS * NFRAG];

__device__ __align__(16) __half g_af [B_ROWS * IN_F];   // fp16(x * p)
__device__ __align__(16) __half g_mf [B_ROWS * IN_F];   // fp16(x - x*p)
__device__ __align__(16) __half g_wth[OUT_F * IN_F];    // We^T  [N,K]
__device__ __align__(16) __half g_wch[COMP * IN_F];     // Wc    [N,K]
__device__ __align__(16) __half g_wnh[OUT_F * COMP];    // Wn    [N,K]
__device__ __align__(16) __half g_c1f[B_ROWS * COMP];   // fp16 compressed

// ---------------------------------------------------------------------------
// Helpers (family-safe PTX only: cp.async, ldmatrix, fp16 mma.sync)
// ---------------------------------------------------------------------------
__device__ __forceinline__ uint32_t smem_u32(const void* p) {
    uint32_t a;
    asm("{ .reg .u64 t; cvta.to.shared.u64 t, %1; cvt.u32.u64 %0, t; }"
        : "=r"(a) : "l"(p));
    return a;
}
__device__ __forceinline__ void cp16(uint32_t dst, const void* src) {
    asm volatile("cp.async.cg.shared.global [%0], [%1], 16;" :: "r"(dst), "l"(src));
}
__device__ __forceinline__ void cp_commit() {
    asm volatile("cp.async.commit_group;");
}
__device__ __forceinline__ void cp_wait1() {
    asm volatile("cp.async.wait_group 1;" ::: "memory");
}
__device__ __forceinline__ void ldsm4(uint32_t* f, uint32_t a) {
    asm volatile("ldmatrix.sync.aligned.m8n8.x4.shared.b16 {%0,%1,%2,%3}, [%4];"
                 : "=r"(f[0]), "=r"(f[1]), "=r"(f[2]), "=r"(f[3]) : "r"(a));
}
__device__ __forceinline__ void hmma(float* d, const uint32_t* a,
                                     uint32_t b0, uint32_t b1) {
    asm volatile(
        "mma.sync.aligned.m16n8k16.row.col.f32.f16.f16.f32 "
        "{%0,%1,%2,%3}, {%4,%5,%6,%7}, {%8,%9}, {%0,%1,%2,%3};"
        : "+f"(d[0]), "+f"(d[1]), "+f"(d[2]), "+f"(d[3])
        : "r"(a[0]), "r"(a[1]), "r"(a[2]), "r"(a[3]), "r"(b0), "r"(b1));
}
union PackH4 { __half h[4]; uint2 u; };

// ---------------------------------------------------------------------------
// Gating: softmax over fragment scores
// ---------------------------------------------------------------------------
__global__ void __launch_bounds__(512) gating_kernel(
    const float* __restrict__ x, const float* __restrict__ sel)
{
    int b = blockIdx.x, t = threadIdx.x;
    int w = t >> 5, lane = t & 31;
    const float* xr = x + (size_t)b * IN_F + w * FS;
    const float* sr = sel + w * FS;
    float acc = 0.f;
#pragma unroll
    for (int j = 0; j < 8; j++) acc += xr[lane + 32*j] * sr[lane + 32*j];
#pragma unroll
    for (int o = 16; o; o >>= 1) acc += __shfl_xor_sync(0xFFFFFFFFu, acc, o);
    __shared__ float s[NFRAG];
    if (lane == 0) s[w] = acc;
    __syncthreads();
    if (t < NFRAG) {
        float m = -INFINITY;
#pragma unroll
        for (int f = 0; f < NFRAG; f++) m = fmaxf(m, s[f]);
        float sum = 0.f;
#pragma unroll
        for (int f = 0; f < NFRAG; f++) sum += __expf(s[f] - m);
        g_probs[b * NFRAG + t] = __expf(s[t] - m) / sum;
    }
}

// ---------------------------------------------------------------------------
// Prescale: a = x*p, m = x - a; round both to fp16
// ---------------------------------------------------------------------------
__global__ void __launch_bounds__(256) prescale_f16(const float* __restrict__ x)
{
    size_t base = ((size_t)blockIdx.x * blockDim.x + threadIdx.x) * 4;
    int b   = (int)(base >> 12);
    int col = (int)(base & 4095);
    float p = g_probs[b * NFRAG + (col >> 8)];
    float4 v = *(const float4*)(x + base);
    float a0 = v.x*p, a1 = v.y*p, a2 = v.z*p, a3 = v.w*p;
    PackH4 af, mf;
    af.h[0] = __float2half_rn(a0);      af.h[1] = __float2half_rn(a1);
    af.h[2] = __float2half_rn(a2);      af.h[3] = __float2half_rn(a3);
    mf.h[0] = __float2half_rn(v.x-a0);  mf.h[1] = __float2half_rn(v.y-a1);
    mf.h[2] = __float2half_rn(v.z-a2);  mf.h[3] = __float2half_rn(v.w-a3);
    *(uint2*)(g_af + base) = af.u;
    *(uint2*)(g_mf + base) = mf.u;
}

// ---------------------------------------------------------------------------
// Transpose We [K,N] -> WeT [N,K], fp16
// ---------------------------------------------------------------------------
__global__ void __launch_bounds__(256) transpose_we(const float* __restrict__ We)
{
    __shared__ float tile[32][33];
    int k0 = blockIdx.y * 32, n0 = blockIdx.x * 32;
    int tx = threadIdx.x, ty = threadIdx.y;
#pragma unroll
    for (int r = 0; r < 4; r++)
        tile[ty + r*8][tx] = We[(size_t)(k0 + ty + r*8) * OUT_F + n0 + tx];
    __syncthreads();
#pragma unroll
    for (int r = 0; r < 4; r++) {
        size_t o = (size_t)(n0 + ty + r*8) * IN_F + k0 + tx;
        g_wth[o] = __float2half_rn(tile[tx][ty + r*8]);
    }
}

// ---------------------------------------------------------------------------
// Round Wc / Wn to fp16 (already [N,K] K-contiguous)
// ---------------------------------------------------------------------------
__global__ void __launch_bounds__(256) round_h(
    const float* __restrict__ src, __half* __restrict__ hp)
{
    size_t base = ((size_t)blockIdx.x * blockDim.x + threadIdx.x) * 4;
    float4 v = *(const float4*)(src + base);
    PackH4 h;
    h.h[0] = __float2half_rn(v.x); h.h[1] = __float2half_rn(v.y);
    h.h[2] = __float2half_rn(v.z); h.h[3] = __float2half_rn(v.w);
    *(uint2*)(hp + base) = h.u;
}

// ---------------------------------------------------------------------------
// GEMM core: C = A_f16 . B_f16^T    BK=64 stages, single product
// ---------------------------------------------------------------------------
struct SegP {
    const __half *A, *B;
    int ldA, ldB, nt;    // nt = number of BK tiles in this segment
};

// stage load: A 128x64, B 128x64, 128B rows, swizzled (8 cp16 per thread)
__device__ __forceinline__ void load_stage(uint32_t st, const SegP& sg,
                                           int rowBase, int colBase, int kt)
{
    int t = threadIdx.x;
#pragma unroll
    for (int i = 0; i < 4; i++) {
        int id = t + i * 256;
        int r  = id >> 3;
        int c  = id & 7;
        uint32_t off = (uint32_t)(r * 128 + SWZ(r, c));
        cp16(st + off,          sg.A + (size_t)(rowBase + r) * sg.ldA + kt + c * 8);
        cp16(st + TILE_B + off, sg.B + (size_t)(colBase + r) * sg.ldB + kt + c * 8);
    }
}

// compute one BK=64 stage: 4 k16 sub-steps
__device__ __forceinline__ void compute_stage(uint32_t st, float acc[4][4][4],
                                              int wm, int wn, int lane)
{
#pragma unroll
    for (int kk = 0; kk < 4; kk++) {
        int cbase = kk * 2 + (lane >> 4);            // 16B chunk index (0..7)
        uint32_t af[4][4];
#pragma unroll
        for (int mi = 0; mi < 4; mi++) {
            int r = wm * 64 + mi * 16 + (lane & 15);
            uint32_t off = (uint32_t)(r * 128 + SWZ(r, cbase));
            ldsm4(af[mi], st + off);
        }
        uint32_t bf[2][4];
#pragma unroll
        for (int ni = 0; ni < 2; ni++) {
            int r = wn * 32 + ni * 16 + (lane & 15);
            uint32_t off = (uint32_t)(r * 128 + SWZ(r, cbase));
            ldsm4(bf[ni], st + TILE_B + off);
        }
#pragma unroll
        for (int mi = 0; mi < 4; mi++)
#pragma unroll
            for (int g = 0; g < 4; g++) {
                int ni = g >> 1, s = g & 1;
                hmma(acc[mi][g], af[mi], bf[ni][s], bf[ni][s + 2]);
            }
    }
}

// pipelined mainloop over (up to 2) segments; fills acc
__device__ __forceinline__ void run_mainloop(uint32_t sb, const SegP* segs, int nseg,
                                             int rowBase, int colBase,
                                             float acc[4][4][4])
{
    int lane = threadIdx.x & 31, wid = threadIdx.x >> 5;
    int wm = wid >> 2, wn = wid & 3;

    int ntTot = 0;
    for (int s = 0; s < nseg; s++) ntTot += segs[s].nt;

    auto issue = [&](int tile, int stageIdx) {
        int i = tile, s = 0;
        while (s < nseg - 1 && i >= segs[s].nt) { i -= segs[s].nt; s++; }
        load_stage(sb + stageIdx * STAGE_B, segs[s], rowBase, colBase, i * BK);
    };

    issue(0, 0); cp_commit();
    if (ntTot > 1) issue(1, 1);
    cp_commit();

    for (int it = 0; it < ntTot; it++) {
        cp_wait1();
        __syncthreads();
        if (it + 2 < ntTot) issue(it + 2, (it + 2) % NSTAGE);
        cp_commit();
        compute_stage(sb + (it % NSTAGE) * STAGE_B, acc, wm, wn, lane);
        __syncthreads();
    }
}

// ---------------------------------------------------------------------------
// GEMM 1: c1 = m . Wc^T  -> fp16
// ---------------------------------------------------------------------------
__global__ void __launch_bounds__(256, 2) gemm_compress_h(void)
{
    extern __shared__ __align__(128) char smem[];
    uint32_t sb = smem_u32(smem);
    int rowBase = blockIdx.y * BM, colBase = blockIdx.x * BN;

    float acc[4][4][4];
#pragma unroll
    for (int a = 0; a < 4; a++)
#pragma unroll
        for (int b = 0; b < 4; b++)
#pragma unroll
            for (int c = 0; c < 4; c++) acc[a][b][c] = 0.f;

    SegP segs[1] = { { g_mf, g_wch, IN_F, IN_F, IN_F / BK } };
    run_mainloop(sb, segs, 1, rowBase, colBase, acc);

    int lane = threadIdx.x & 31, wid = threadIdx.x >> 5;
    int wm = wid >> 2, wn = wid & 3;
#pragma unroll
    for (int mi = 0; mi < 4; mi++)
#pragma unroll
        for (int g = 0; g < 4; g++) {
            int r0 = rowBase + wm * 64 + mi * 16 + (lane >> 2);
            int c0 = colBase + wn * 32 + g * 8 + (lane & 3) * 2;
            __half2 v0 = __floats2half2_rn(acc[mi][g][0], acc[mi][g][1]);
            __half2 v1 = __floats2half2_rn(acc[mi][g][2], acc[mi][g][3]);
            *(__half2*)(g_c1f + (size_t)r0 * COMP + c0)       = v0;
            *(__half2*)(g_c1f + (size_t)(r0 + 8) * COMP + c0) = v1;
        }
}

// ---------------------------------------------------------------------------
// GEMM 2 (fused): out = a . We  +  c1 . Wn^T
// ---------------------------------------------------------------------------
__global__ void __launch_bounds__(256, 2) gemm_out_h(float* __restrict__ out)
{
    extern __shared__ __align__(128) char smem[];
    uint32_t sb = smem_u32(smem);
    int rowBase = blockIdx.y * BM, colBase = blockIdx.x * BN;

    float acc[4][4][4];
#pragma unroll
    for (int a = 0; a < 4; a++)
#pragma unroll
        for (int b = 0; b < 4; b++)
#pragma unroll
            for (int c = 0; c < 4; c++) acc[a][b][c] = 0.f;

    SegP segs[2] = {
        { g_af,  g_wth, IN_F, IN_F, IN_F / BK },
        { g_c1f, g_wnh, COMP, COMP, COMP / BK },
    };
    run_mainloop(sb, segs, 2, rowBase, colBase, acc);

    int lane = threadIdx.x & 31, wid = threadIdx.x >> 5;
    int wm = wid >> 2, wn = wid & 3;
#pragma unroll
    for (int mi = 0; mi < 4; mi++)
#pragma unroll
        for (int g = 0; g < 4; g++) {
            int r0 = rowBase + wm * 64 + mi * 16 + (lane >> 2);
            int c0 = colBase + wn * 32 + g * 8 + (lane & 3) * 2;
            *(float2*)(out + (size_t)r0 * OUT_F + c0) =
                make_float2(acc[mi][g][0], acc[mi][g][1]);
            *(float2*)(out + (size_t)(r0 + 8) * OUT_F + c0) =
                make_float2(acc[mi][g][2], acc[mi][g][3]);
        }
}

// ---------------------------------------------------------------------------
// Launch
// ---------------------------------------------------------------------------
extern "C" void kernel_launch(void* const* d_in, const int* in_sizes, int n_in,
                              void* d_out, int out_size)
{
    const float* x   = (const float*)d_in[0];   // [8192, 4096]
    const float* sel = (const float*)d_in[1];   // [16, 256]
    const float* We  = (const float*)d_in[2];   // [4096, 4096]  (K,N)
    const float* Wc  = (const float*)d_in[3];   // [1024, 4096]  (N,K)
    const float* Wn  = (const float*)d_in[4];   // [4096, 1024]  (N,K)
    float* out = (float*)d_out;                 // [8192, 4096]

    __half *wch, *wnh;
    cudaGetSymbolAddress((void**)&wch, g_wch);
    cudaGetSymbolAddress((void**)&wnh, g_wnh);

    cudaFuncSetAttribute(gemm_compress_h, cudaFuncAttributeMaxDynamicSharedMemorySize, SMEM_DYN);
    cudaFuncSetAttribute(gemm_out_h,      cudaFuncAttributeMaxDynamicSharedMemorySize, SMEM_DYN);

    gating_kernel<<<B_ROWS, 512>>>(x, sel);
    prescale_f16<<<(B_ROWS * (IN_F / 4)) / 256, 256>>>(x);
    transpose_we<<<dim3(OUT_F / 32, IN_F / 32), dim3(32, 8)>>>(We);
    round_h<<<(COMP * (IN_F / 4)) / 256, 256>>>(Wc, wch);
    round_h<<<(OUT_F * (COMP / 4)) / 256, 256>>>(Wn, wnh);

    gemm_compress_h<<<dim3(COMP / BN, B_ROWS / BM), 256, SMEM_DYN>>>();
    gemm_out_h<<<dim3(OUT_F / BN, B_ROWS / BM), 256, SMEM_DYN>>>(out);
}